// round 17
// baseline (speedup 1.0000x reference)
#include <cuda_runtime.h>
#include <cuda_fp16.h>
#include <cstdint>
#include <math.h>

#define BN    8
#define CINC  256
#define CMID  128
#define COUTC 256
#define HH    128
#define WW    128
#define HWSZ  16384

typedef uint32_t u32;

// ---------------- scratch (static __device__ — allocation-free) ----------------
__device__ __half g_yh[4][BN * CMID * HH * WW];  // branch conv outputs (post-relu, fp16)
__device__ __half g_Sh[BN * CMID * HH * WW];     // scanned sum (fp16)
// fp16 weights (single plane): branch [tap=br*9+kh*3+kw][co=128][cipair=128]
__device__ __align__(16) __half2 g_wA[36 * 128 * 128];
__device__ __align__(16) __half2 g_w2[9 * 256 * 64];   // [t][co=256][cipair=64]
__device__ __align__(16) __half2 g_w1[256 * 128];      // [co=256][cipair=128]

// ---------------- helpers ----------------
__device__ __forceinline__ u32 smem_u32(const void* p) {
    u32 a;
    asm("{ .reg .u64 t; cvta.to.shared.u64 t, %1; cvt.u32.u64 %0, t; }" : "=r"(a) : "l"(p));
    return a;
}

// XOR swizzle: byte bits [6:4] ^= bits [9:7]  (rows are 128B)
#define SWZ(off) ((off) ^ (((off) >> 3) & 0x70))

__device__ __forceinline__ void ldm_x4(u32* r, u32 addr) {
    asm volatile("ldmatrix.sync.aligned.m8n8.x4.shared.b16 {%0,%1,%2,%3}, [%4];"
                 : "=r"(r[0]), "=r"(r[1]), "=r"(r[2]), "=r"(r[3]) : "r"(addr));
}
__device__ __forceinline__ void mma16816(float* d, const u32* a, const u32* b) {
    asm volatile("mma.sync.aligned.m16n8k16.row.col.f32.f16.f16.f32 "
                 "{%0,%1,%2,%3}, {%4,%5,%6,%7}, {%8,%9}, {%0,%1,%2,%3};"
                 : "+f"(d[0]), "+f"(d[1]), "+f"(d[2]), "+f"(d[3])
                 : "r"(a[0]), "r"(a[1]), "r"(a[2]), "r"(a[3]), "r"(b[0]), "r"(b[1]));
}
__device__ __forceinline__ void cpa16(u32 d, const void* s) {
    asm volatile("cp.async.cg.shared.global [%0], [%1], 16;" :: "r"(d), "l"(s));
}
#define CPA_COMMIT() asm volatile("cp.async.commit_group;" ::: "memory")
#define CPA_WAIT0()  asm volatile("cp.async.wait_group 0;" ::: "memory")
#define PAIR_BAR(id) asm volatile("bar.sync %0, 64;" :: "r"(id) : "memory")

// smem (per CTA, sized for 2 CTAs/SM): two A buffers (128 rows) + two B buffers (132 rows)
#define BSZ    16896                    // 132 * 128 bytes
#define OFF_A0 0
#define OFF_A1 16384
#define OFF_B0 32768
#define OFF_B1 (32768 + BSZ)            // 49664
#define SMEM_BYTES (OFF_B1 + BSZ)       // 66560
#define SCAN_SMEM 65536                 // 128x128 fp32 S plane

// pack two fp32 -> fp16x2 word and store to smem
__device__ __forceinline__ void stpack(float v0, float v1, u32 addr) {
    __half h0 = __float2half(v0), h1 = __float2half(v1);
    u32 hv;
    asm("mov.b32 %0, {%1, %2};" : "=r"(hv) : "h"(*(unsigned short*)&h0), "h"(*(unsigned short*)&h1));
    asm volatile("st.shared.b32 [%0], %1;" :: "r"(addr), "r"(hv) : "memory");
}
// pack two fp16 -> fp16x2 word and store to smem (no cvt)
__device__ __forceinline__ void stpackh(__half v0, __half v1, u32 addr) {
    u32 hv;
    asm("mov.b32 %0, {%1, %2};" : "=r"(hv) : "h"(*(unsigned short*)&v0), "h"(*(unsigned short*)&v1));
    asm volatile("st.shared.b32 [%0], %1;" :: "r"(addr), "r"(hv) : "memory");
}

// ---------------- merged weight repack (+BN scale fold, fp16) ----------------
// blocks [0,2304): branch weights; [2304,2880): w2; [2880,3008): w1
__global__ void k_repack_all(
    const float* __restrict__ w_l, const float* __restrict__ s_l,
    const float* __restrict__ w_r, const float* __restrict__ s_r,
    const float* __restrict__ w_t, const float* __restrict__ s_t,
    const float* __restrict__ w_b, const float* __restrict__ s_b,
    const float* __restrict__ w2,  const float* __restrict__ s2,
    const float* __restrict__ w1,  const float* __restrict__ s1)
{
    int blk = blockIdx.x;
    if (blk < 2304) {
        int br = blk / 576;
        int slot = (blk - br * 576) * 256 + threadIdx.x;   // 9*128*128
        if (slot >= 147456) return;
        const float* w = (br == 0) ? w_l : (br == 1) ? w_r : (br == 2) ? w_t : w_b;
        const float* s = (br == 0) ? s_l : (br == 1) ? s_r : (br == 2) ? s_t : s_b;
        int pair = slot & 127;
        int co   = (slot >> 7) & 127;
        int t    = slot >> 14;
        int kh = t / 3, kw = t % 3;
        int ci = pair * 2;
        float sc = s[co];
        float v0 = w[((co * CINC + ci)     * 3 + kh) * 3 + kw] * sc;
        float v1 = w[((co * CINC + ci + 1) * 3 + kh) * 3 + kw] * sc;
        g_wA[((br * 9 + t) * 128 + co) * 128 + pair] =
            __halves2half2(__float2half(v0), __float2half(v1));
    } else if (blk < 2880) {
        int slot = (blk - 2304) * 256 + threadIdx.x;       // 9*256*64
        if (slot >= 147456) return;
        int pair = slot & 63;
        int co   = (slot >> 6) & 255;
        int t    = slot >> 14;
        int kh = t / 3, kw = t % 3;
        int ci = pair * 2;
        float sc = s2[co];
        float v0 = w2[((co * CMID + ci)     * 3 + kh) * 3 + kw] * sc;
        float v1 = w2[((co * CMID + ci + 1) * 3 + kh) * 3 + kw] * sc;
        g_w2[(t * 256 + co) * 64 + pair] =
            __halves2half2(__float2half(v0), __float2half(v1));
    } else {
        int slot = (blk - 2880) * 256 + threadIdx.x;       // 256*128
        if (slot >= 32768) return;
        int pair = slot & 127;
        int co   = slot >> 7;
        int ci = pair * 2;
        float sc = s1[co];
        float v0 = w1[co * CINC + ci]     * sc;
        float v1 = w1[co * CINC + ci + 1] * sc;
        g_w1[co * 128 + pair] =
            __halves2half2(__float2half(v0), __float2half(v1));
    }
}

// ---------------- per-warp A copy: 16 rows x 128B (8 warps cover M=128) ----------------
__device__ __forceinline__ void build_A_warp(u32 sb, u32 offA, int wm, int wn, int lane,
                                             const __half2* __restrict__ wsrc,
                                             int rsp, int pair0)
{
#pragma unroll
    for (int q = 0; q < 4; q++) {
        int slot = lane + 32 * q;            // 0..127
        int co = wm * 32 + wn * 16 + (slot >> 3);   // 0..127
        int c  = slot & 7;
        u32 d = SWZ((u32)(co * 128 + c * 16));
        cpa16(sb + offA + d, (const char*)(wsrc + (size_t)co * rsp + pair0) + c * 16);
    }
}

// ---------------- direct B build: fp32 src -> fp16 swizzled tile (132 rows) ----------------
__device__ __forceinline__ void build_B_direct(u32 sb, u32 offB, int tid,
                                               const float* __restrict__ src,
                                               int nchan, int b, int c0, int srow)
{
    const size_t HW = (size_t)HWSZ;
    bool rowok = (srow >= 0) && (srow < HH);
    const float* base = src + ((size_t)(b * nchan + c0) * HH + (rowok ? srow : 0)) * WW;
    int p  = tid & 127;
    int gp = tid >> 7;                       // 0..1
    int spx = p - 1;
    bool okm = rowok && (spx >= 0);
    const float* bp = base + spx;
#pragma unroll
    for (int q = 0; q < 16; q++) {
        int cil = gp * 32 + 2 * q;
        float v0 = okm ? bp[(size_t)cil * HW] : 0.f;
        float v1 = okm ? bp[(size_t)(cil + 1) * HW] : 0.f;
        stpack(v0, v1, sb + offB + SWZ((u32)(p * 128 + 2 * cil)));
    }
    if (tid < 128) {                         // tail rows 128..131 (src px 127..130)
        int rr = 128 + (tid >> 5);
        int pc = tid & 31;
        int sp2 = rr - 1;
        bool ok = rowok && (sp2 < WW);
        float v0 = ok ? base[(size_t)(2 * pc) * HW + sp2] : 0.f;
        float v1 = ok ? base[(size_t)(2 * pc + 1) * HW + sp2] : 0.f;
        stpack(v0, v1, sb + offB + SWZ((u32)(rr * 128 + 4 * pc)));
    }
}

// ---------------- B build from fp16 source (no cvt) ----------------
__device__ __forceinline__ void build_B_half(u32 sb, u32 offB, int tid,
                                             const __half* __restrict__ src,
                                             int nchan, int b, int c0, int srow)
{
    const size_t HW = (size_t)HWSZ;
    bool rowok = (srow >= 0) && (srow < HH);
    const __half* base = src + ((size_t)(b * nchan + c0) * HH + (rowok ? srow : 0)) * WW;
    int p  = tid & 127;
    int gp = tid >> 7;
    int spx = p - 1;
    bool okm = rowok && (spx >= 0);
    const __half* bp = base + spx;
    const __half hz = __float2half(0.f);
#pragma unroll
    for (int q = 0; q < 16; q++) {
        int cil = gp * 32 + 2 * q;
        __half v0 = okm ? bp[(size_t)cil * HW] : hz;
        __half v1 = okm ? bp[(size_t)(cil + 1) * HW] : hz;
        stpackh(v0, v1, sb + offB + SWZ((u32)(p * 128 + 2 * cil)));
    }
    if (tid < 128) {
        int rr = 128 + (tid >> 5);
        int pc = tid & 31;
        int sp2 = rr - 1;
        bool ok = rowok && (sp2 < WW);
        __half v0 = ok ? base[(size_t)(2 * pc) * HW + sp2] : hz;
        __half v1 = ok ? base[(size_t)(2 * pc + 1) * HW + sp2] : hz;
        stpackh(v0, v1, sb + offB + SWZ((u32)(rr * 128 + 4 * pc)));
    }
}

// ---------------- mma over one 64-k chunk; M=128, warp = 32co x 64px ----------------
// 8 warps: wm = wid>>1 (0..3), wn = wid&1 (0..1)
__device__ __forceinline__ void mma_chunk(u32 sb, u32 offA, u32 offB, int kw,
                                          int wm, int wn, int lid, float acc[2][8][4])
{
    const u32 lrow  = (u32)(lid & 15) * 128;
    const u32 lkh   = (u32)((lid >> 4) << 4);
    const u32 brow0 = (u32)kw * 128 + lrow;
#pragma unroll
    for (int ks = 0; ks < 4; ks++) {
        const u32 kb = (u32)(ks * 32) + lkh;
        u32 ah[2][4], bh[4][4];
#pragma unroll
        for (int mt = 0; mt < 2; mt++) {
            u32 off = SWZ((u32)((wm * 32 + mt * 16) * 128) + lrow + kb);
            ldm_x4(ah[mt], sb + offA + off);
        }
#pragma unroll
        for (int bt = 0; bt < 4; bt++) {
            u32 off = SWZ((u32)((wn * 64 + bt * 16) * 128) + brow0 + kb);
            ldm_x4(bh[bt], sb + offB + off);
        }
#pragma unroll
        for (int mt = 0; mt < 2; mt++)
#pragma unroll
            for (int bt = 0; bt < 4; bt++)
#pragma unroll
                for (int j = 0; j < 2; j++) {
                    u32 BH2[2] = { bh[bt][j], bh[bt][j + 2] };
                    mma16816(acc[mt][bt * 2 + j], ah[mt], BH2);
                }
    }
}

// ---------------- 3x3 branch conv + BN + relu -> g_yh[br] (fp16) ----------------
// grid = (H=128, B=8, br=4), 256 threads, 2 CTAs/SM
__global__ __launch_bounds__(256, 2)
void k_conv_branch(const float* __restrict__ x,
                   const float* __restrict__ ob0, const float* __restrict__ ob1,
                   const float* __restrict__ ob2, const float* __restrict__ ob3)
{
    extern __shared__ char smem_raw[];
    u32 sb = smem_u32(smem_raw);
    const int h  = blockIdx.x;
    const int b  = blockIdx.y;
    const int br = blockIdx.z;
    const int tid = threadIdx.x;
    const int wid = tid >> 5, lid = tid & 31;
    const int wm = wid >> 1, wn = wid & 1;

    float acc[2][8][4];
#pragma unroll
    for (int i = 0; i < 2; i++)
#pragma unroll
        for (int j = 0; j < 8; j++)
#pragma unroll
            for (int k = 0; k < 4; k++) acc[i][j][k] = 0.f;

    build_A_warp(sb, OFF_A0, wm, wn, lid, g_wA + (size_t)(br * 9) * 16384, 128, 0);
    CPA_COMMIT();

    for (int ch = 0; ch < 12; ch++) {
        int kh = ch >> 2, c0 = (ch & 3) * 64;
        u32 offB = (ch & 1) ? OFF_B1 : OFF_B0;
        build_B_direct(sb, offB, tid, x, CINC, b, c0, h + kh - 1);
        __syncthreads();
#pragma unroll
        for (int kw = 0; kw < 3; kw++) {
            int step = ch * 3 + kw;
            CPA_WAIT0();
            PAIR_BAR(1 + wm);
            if (step + 1 < 36) {
                int s2 = step + 1, ch2 = s2 / 3, kw2 = s2 - ch2 * 3;
                int kh2 = ch2 >> 2, c02 = (ch2 & 3) * 64;
                build_A_warp(sb, (s2 & 1) ? OFF_A1 : OFF_A0, wm, wn, lid,
                             g_wA + (size_t)(br * 9 + kh2 * 3 + kw2) * 16384, 128, c02 >> 1);
                CPA_COMMIT();
            }
            mma_chunk(sb, (step & 1) ? OFF_A1 : OFF_A0, offB, kw, wm, wn, lid, acc);
        }
    }

    const float* ob = (br == 0) ? ob0 : (br == 1) ? ob1 : (br == 2) ? ob2 : ob3;
    __half* yb = g_yh[br];
#pragma unroll
    for (int mt = 0; mt < 2; mt++) {
#pragma unroll
        for (int half = 0; half < 2; half++) {
            int co = wm * 32 + mt * 16 + half * 8 + (lid >> 2);   // 0..127
            float sh = ob[co];
            __half* row = yb + ((size_t)(b * CMID + co) * HH + h) * WW;
#pragma unroll
            for (int nf = 0; nf < 8; nf++) {
                int px = wn * 64 + nf * 8 + 2 * (lid & 3);
                float2 v;
                v.x = fmaxf(acc[mt][nf][half * 2 + 0] + sh, 0.f);
                v.y = fmaxf(acc[mt][nf][half * 2 + 1] + sh, 0.f);
                *(__half2*)(row + px) = __float22half2_rn(v);
            }
        }
    }
}

// ---------------- fused scans: S = revmax_w(L)+fwdmax_w(R)+revmax_h(T)+fwdmax_h(B) -------
// grid = BN*CMID (one (b,c) plane per CTA), 512 threads, 64KB smem S-plane
__global__ __launch_bounds__(512)
void k_scan_fused()
{
    extern __shared__ float smf[];           // 128 x 128 fp32
    int bc   = blockIdx.x;
    int tid  = threadIdx.x;
    int wq   = tid >> 5;
    int lane = tid & 31;
    const size_t plane = (size_t)bc * HWSZ;

    // phase 1: w-scans (warp per row, 8 rows per warp)
#pragma unroll
    for (int i = 0; i < 8; i++) {
        int hr = wq + 16 * i;
        const __half2* yl2 = (const __half2*)(g_yh[0] + plane + (size_t)hr * WW);
        const __half2* yr2 = (const __half2*)(g_yh[1] + plane + (size_t)hr * WW);
        __half2 a01 = yl2[lane * 2], a23 = yl2[lane * 2 + 1];
        __half2 r01 = yr2[lane * 2], r23 = yr2[lane * 2 + 1];
        float ax = __low2float(a01), ay = __high2float(a01);
        float az = __low2float(a23), aw = __high2float(a23);
        float rx = __low2float(r01), ry = __high2float(r01);
        float rz = __low2float(r23), rw = __high2float(r23);
        float p0 = rx, p1 = fmaxf(p0, ry), p2 = fmaxf(p1, rz), p3 = fmaxf(p2, rw);
        float m = p3;
#pragma unroll
        for (int o = 1; o < 32; o <<= 1) {
            float v = __shfl_up_sync(0xffffffffu, m, o);
            if (lane >= o) m = fmaxf(m, v);
        }
        float ex = __shfl_up_sync(0xffffffffu, m, 1);
        if (lane == 0) ex = -INFINITY;
        float q3 = aw, q2 = fmaxf(q3, az), q1 = fmaxf(q2, ay), q0 = fmaxf(q1, ax);
        float mm = q0;
#pragma unroll
        for (int o = 1; o < 32; o <<= 1) {
            float v = __shfl_down_sync(0xffffffffu, mm, o);
            if (lane + o < 32) mm = fmaxf(mm, v);
        }
        float exr = __shfl_down_sync(0xffffffffu, mm, 1);
        if (lane == 31) exr = -INFINITY;
        float4 o4;
        o4.x = fmaxf(ex, p0) + fmaxf(exr, q0);
        o4.y = fmaxf(ex, p1) + fmaxf(exr, q1);
        o4.z = fmaxf(ex, p2) + fmaxf(exr, q2);
        o4.w = fmaxf(ex, p3) + fmaxf(exr, q3);
        *(float4*)&smf[hr * 128 + lane * 4] = o4;
    }
    __syncthreads();

    // phase 2: h-scans per column (threads 0..127), emit fp16
    if (tid < 128) {
        int w = tid;
        const __half* yt = g_yh[2] + plane + w;
        const __half* yv = g_yh[3] + plane + w;
        __half* Sp = g_Sh + plane + w;
        float m = -INFINITY;
        for (int hq = HH - 1; hq >= 0; --hq) {
            m = fmaxf(m, __half2float(yt[hq * WW]));
            smf[hq * 128 + w] += m;
        }
        m = -INFINITY;
        for (int hq = 0; hq < HH; ++hq) {
            m = fmaxf(m, __half2float(yv[hq * WW]));
            Sp[hq * WW] = __float2half(smf[hq * 128 + w] + m);
        }
    }
}

// ---------------- conv2 3x3 over S(fp16) + 1x1 skip over x + relu -> out ----------------
// grid = (H=128, B=8, ct=2), 256 threads, 2 CTAs/SM
__device__ __forceinline__ void prefetch_A_out_warp(u32 sb, int wm, int wn, int lane,
                                                    int ct, int s)
{
    u32 offA = (s & 1) ? OFF_A1 : OFF_A0;
    if (s < 18) {
        int ch = s / 3, kw = s - ch * 3;
        int kh = ch >> 1, c0 = (ch & 1) * 64;
        build_A_warp(sb, offA, wm, wn, lane,
                     g_w2 + ((size_t)(kh * 3 + kw) * 256 + ct * 128) * 64, 64, c0 >> 1);
    } else {
        int c = s - 18;
        build_A_warp(sb, offA, wm, wn, lane,
                     g_w1 + (size_t)ct * 128 * 128, 128, c * 32);
    }
    CPA_COMMIT();
}

__global__ __launch_bounds__(256, 2)
void k_conv_out(const float* __restrict__ x,
                const float* __restrict__ o2v, const float* __restrict__ o1v,
                float* __restrict__ out)
{
    extern __shared__ char smem_raw[];
    u32 sb = smem_u32(smem_raw);
    const int h  = blockIdx.x;
    const int b  = blockIdx.y;
    const int ct = blockIdx.z;
    const int tid = threadIdx.x;
    const int wid = tid >> 5, lid = tid & 31;
    const int wm = wid >> 1, wn = wid & 1;

    float acc[2][8][4];
#pragma unroll
    for (int i = 0; i < 2; i++)
#pragma unroll
        for (int j = 0; j < 8; j++)
#pragma unroll
            for (int k = 0; k < 4; k++) acc[i][j][k] = 0.f;

    prefetch_A_out_warp(sb, wm, wn, lid, ct, 0);

    // phase 1: 3x3 conv over g_Sh (6 chunks x 3 kw = 18 steps)
    for (int ch = 0; ch < 6; ch++) {
        int kh = ch >> 1, c0 = (ch & 1) * 64;
        u32 offB = (ch & 1) ? OFF_B1 : OFF_B0;
        build_B_half(sb, offB, tid, g_Sh, CMID, b, c0, h + kh - 1);
        __syncthreads();
#pragma unroll
        for (int kw = 0; kw < 3; kw++) {
            int step = ch * 3 + kw;
            CPA_WAIT0();
            PAIR_BAR(1 + wm);
            if (step + 1 < 22) prefetch_A_out_warp(sb, wm, wn, lid, ct, step + 1);
            mma_chunk(sb, (step & 1) ? OFF_A1 : OFF_A0, offB, kw, wm, wn, lid, acc);
        }
    }
    // phase 2: 1x1 skip over x (4 chunks; brow offset 1 = unshifted pixels)
    for (int c = 0; c < 4; c++) {
        int ch = 6 + c;
        u32 offB = (ch & 1) ? OFF_B1 : OFF_B0;
        build_B_direct(sb, offB, tid, x, CINC, b, c * 64, h);
        __syncthreads();
        int step = 18 + c;
        CPA_WAIT0();
        PAIR_BAR(1 + wm);
        if (step + 1 < 22) prefetch_A_out_warp(sb, wm, wn, lid, ct, step + 1);
        mma_chunk(sb, (step & 1) ? OFF_A1 : OFF_A0, offB, 1, wm, wn, lid, acc);
    }

#pragma unroll
    for (int mt = 0; mt < 2; mt++) {
#pragma unroll
        for (int half = 0; half < 2; half++) {
            int co = ct * 128 + wm * 32 + mt * 16 + half * 8 + (lid >> 2);
            float sh = o2v[co] + o1v[co];
            float* row = out + ((size_t)(b * COUTC + co) * HH + h) * WW;
#pragma unroll
            for (int nf = 0; nf < 8; nf++) {
                int px = wn * 64 + nf * 8 + 2 * (lid & 3);
                float2 v;
                v.x = fmaxf(acc[mt][nf][half * 2 + 0] + sh, 0.f);
                v.y = fmaxf(acc[mt][nf][half * 2 + 1] + sh, 0.f);
                *(float2*)(row + px) = v;
            }
        }
    }
}

// ---------------- launch ----------------
extern "C" void kernel_launch(void* const* d_in, const int* in_sizes, int n_in,
                              void* d_out, int out_size)
{
    const float* x   = (const float*)d_in[0];
    const float* w_l = (const float*)d_in[1];
    const float* s_l = (const float*)d_in[2];
    const float* o_l = (const float*)d_in[3];
    const float* w_r = (const float*)d_in[4];
    const float* s_r = (const float*)d_in[5];
    const float* o_r = (const float*)d_in[6];
    const float* w_t = (const float*)d_in[7];
    const float* s_t = (const float*)d_in[8];
    const float* o_t = (const float*)d_in[9];
    const float* w_b = (const float*)d_in[10];
    const float* s_b = (const float*)d_in[11];
    const float* o_b = (const float*)d_in[12];
    const float* w2  = (const float*)d_in[13];
    const float* s2  = (const float*)d_in[14];
    const float* o2  = (const float*)d_in[15];
    const float* w1  = (const float*)d_in[16];
    const float* s1  = (const float*)d_in[17];
    const float* o1  = (const float*)d_in[18];
    float* out = (float*)d_out;

    cudaFuncSetAttribute(k_conv_branch, cudaFuncAttributeMaxDynamicSharedMemorySize, SMEM_BYTES);
    cudaFuncSetAttribute(k_conv_out,    cudaFuncAttributeMaxDynamicSharedMemorySize, SMEM_BYTES);
    cudaFuncSetAttribute(k_scan_fused,  cudaFuncAttributeMaxDynamicSharedMemorySize, SCAN_SMEM);

    k_repack_all<<<3008, 256>>>(w_l, s_l, w_r, s_r, w_t, s_t, w_b, s_b, w2, s2, w1, s1);
    dim3 g1(HH, BN, 4);
    k_conv_branch<<<g1, 256, SMEM_BYTES>>>(x, o_l, o_r, o_t, o_b);
    k_scan_fused<<<BN * CMID, 512, SCAN_SMEM>>>();
    dim3 g3(HH, BN, 2);
    k_conv_out<<<g3, 256, SMEM_BYTES>>>(x, o2, o1, out);
}